// round 7
// baseline (speedup 1.0000x reference)
#include <cuda_runtime.h>
#include <cstdint>

// Problem constants (fixed by reference setup_inputs)
#define B_   4
#define N_   16384
#define C_   64
#define NQ_  256
#define NS_  32

// Output layout (verified passing since R1):
//   grouped_xyz : [B, 3,   NQ, NS]
//   new_features: [B, 3+C, NQ, NS]
//   mask        : [B, NQ, NS]  (all False; index 0 can only land in slot 0,
//                               which the reference forces to False)

__global__ __launch_bounds__(256) void boxquery_group_kernel(
    const float* __restrict__ xyz,    // [B, N, 3]
    const float* __restrict__ feat,   // [B, C, N]
    const float* __restrict__ qbox,   // [B, NQ, 6]
    float* __restrict__ out)
{
    const int bq   = blockIdx.x;        // 0 .. B*NQ-1
    const int b    = bq >> 8;           // / NQ_
    const int q    = bq & (NQ_ - 1);
    const int tid  = threadIdx.x;
    const int lane = tid & 31;
    const int w    = tid >> 5;

    // Per-warp selected indices (each warp computes its own identical copy —
    // removes ALL block-level barriers).
    __shared__ __align__(16) int   sidx[8][NS_];
    __shared__ __align__(16) float sgx[3][NS_];   // warp 0 only

    const float* xb  = xyz + (size_t)b * N_ * 3;
    const float4* xb4 = (const float4*)xb;        // batch base is 16B-aligned

    // ---- Front-batched loads (no dependencies): 6 xyz vectors + box ----
    float4 f0 = xb4[6 * lane + 0];
    float4 f1 = xb4[6 * lane + 1];
    float4 f2 = xb4[6 * lane + 2];
    float4 f3 = xb4[6 * lane + 3];
    float4 f4 = xb4[6 * lane + 4];
    float4 f5 = xb4[6 * lane + 5];

    const float2* box2 = (const float2*)(qbox + (size_t)(b * NQ_ + q) * 6);
    const float2 b0 = box2[0];   // cx, cy
    const float2 b1 = box2[1];   // cz, sx
    const float2 b2 = box2[2];   // sy, sz
    const float cx = b0.x, cy = b0.y, cz = b1.x;
    const float hx = 0.5f * b1.y, hy = 0.5f * b2.x, hz = 0.5f * b2.y;

    // lane ℓ holds points 8ℓ..8ℓ+7:  coords of local point t are
    // floats [3t, 3t+1, 3t+2] of (f0..f5).
    float px[8], py[8], pz[8];
    px[0]=f0.x; py[0]=f0.y; pz[0]=f0.z;
    px[1]=f0.w; py[1]=f1.x; pz[1]=f1.y;
    px[2]=f1.z; py[2]=f1.w; pz[2]=f2.x;
    px[3]=f2.y; py[3]=f2.z; pz[3]=f2.w;
    px[4]=f3.x; py[4]=f3.y; pz[4]=f3.z;
    px[5]=f3.w; py[5]=f4.x; pz[5]=f4.y;
    px[6]=f4.z; py[6]=f4.w; pz[6]=f5.x;
    px[7]=f5.y; py[7]=f5.z; pz[7]=f5.w;

    // predicate ("sort key == 0"): (n == 0) || !in_box(n)
    unsigned bits = 0;
    #pragma unroll
    for (int t = 0; t < 8; ++t) {
        const bool inb = (fabsf(px[t] - cx) <= hx) &
                         (fabsf(py[t] - cy) <= hy) &
                         (fabsf(pz[t] - cz) <= hz);
        if (!inb) bits |= (1u << t);
    }
    if (lane == 0) bits |= 1u;          // n == 0 always has zero key

    // ---- In-warp exclusive scan of per-lane counts (5 shfl) ----
    const int cnt = __popc(bits);
    int inc = cnt;
    #pragma unroll
    for (int d = 1; d < 32; d <<= 1) {
        const int t = __shfl_up_sync(0xffffffffu, inc, d);
        if (lane >= d) inc += t;
    }
    const int excl  = inc - cnt;
    const int total = __shfl_sync(0xffffffffu, inc, 31);

    // ---- Scatter first NS_ selected indices (ascending n) into sidx[w] ----
    {
        unsigned bb = bits;
        int s = excl;
        while (bb && s < NS_) {
            const int t = __ffs(bb) - 1;
            sidx[w][s] = 8 * lane + t;
            bb &= bb - 1;
            ++s;
        }
    }

    // ---- Fallback (statistically never taken): exact argsort order over
    // the remaining range, per-warp. Zero-key entries ascending over [256,N),
    // then in-box (n>0) ascending over [0,N). ----
    if (total < NS_) {
        int count = total, base = 256;
        while (count < NS_ && base < N_) {
            const int nn = base + lane;
            const bool inb = (fabsf(xb[nn*3+0] - cx) <= hx) &
                             (fabsf(xb[nn*3+1] - cy) <= hy) &
                             (fabsf(xb[nn*3+2] - cz) <= hz);
            const bool acc = !inb;   // nn > 0 guaranteed
            const unsigned m   = __ballot_sync(0xffffffffu, acc);
            const int      pre = __popc(m & ((1u << lane) - 1u));
            if (acc && (count + pre) < NS_) sidx[w][count + pre] = nn;
            count += __popc(m);
            base  += 32;
        }
        base = 0;
        while (count < NS_ && base < N_) {
            const int nn = base + lane;
            const bool inb = (fabsf(xb[nn*3+0] - cx) <= hx) &
                             (fabsf(xb[nn*3+1] - cy) <= hy) &
                             (fabsf(xb[nn*3+2] - cz) <= hz);
            const bool acc = (nn != 0) && inb;
            const unsigned m   = __ballot_sync(0xffffffffu, acc);
            const int      pre = __popc(m & ((1u << lane) - 1u));
            if (acc && (count + pre) < NS_) sidx[w][count + pre] = nn;
            count += __popc(m);
            base  += 32;
        }
    }
    __syncwarp();

    // ---- Output pointers ----
    float* out_gx = out;                                        // [B,3,NQ,NS]
    float* out_nf = out + (size_t)B_ * 3 * NQ_ * NS_;           // [B,3+C,NQ,NS]
    float* out_mk = out_nf + (size_t)B_ * (3 + C_) * NQ_ * NS_; // [B,NQ,NS]

    // ---- Warp 0: grouped_xyz (rows 0..2 of both tensors) + mask ----
    if (w == 0) {
        const int n = sidx[0][lane];
        sgx[0][lane] = xb[n * 3 + 0] - cx;   // L1-hit reloads
        sgx[1][lane] = xb[n * 3 + 1] - cy;
        sgx[2][lane] = xb[n * 3 + 2] - cz;
        __syncwarp();
        if (lane < 24) {
            const int d = lane >> 3, g = lane & 7;
            const float4 v = ((const float4*)&sgx[0][0])[d * 8 + g];
            ((float4*)(out_gx + ((size_t)(b * 3 + d) * NQ_ + q) * NS_))[g]        = v;
            ((float4*)(out_nf + ((size_t)(b * (3 + C_) + d) * NQ_ + q) * NS_))[g] = v;
        } else {
            ((float4*)(out_mk + (size_t)(b * NQ_ + q) * NS_))[lane - 24] =
                make_float4(0.f, 0.f, 0.f, 0.f);
        }
    }

    // ---- Features: thread t -> channels c0 = t>>3 and c0+32, quad g = t&7 ----
    const float* fb = feat + (size_t)b * C_ * N_;
    const int g  = tid & 7;
    const int c0 = tid >> 3;                         // 0..31
    const int4 nn = ((const int4*)sidx[w])[g];       // own warp's copy (LDS.128)
    float* nf_ch3 = out_nf + ((size_t)(b * (3 + C_) + 3) * NQ_ + q) * NS_;

    #pragma unroll
    for (int pass = 0; pass < 2; ++pass) {
        const int c = c0 + pass * 32;
        const float* fc = fb + (size_t)c * N_;
        float4 v;
        v.x = fc[nn.x];                              // 4 independent LDG.32
        v.y = fc[nn.y];
        v.z = fc[nn.z];
        v.w = fc[nn.w];
        ((float4*)(nf_ch3 + (size_t)c * NQ_ * NS_))[g] = v;   // STG.128
    }
}

extern "C" void kernel_launch(void* const* d_in, const int* in_sizes, int n_in,
                              void* d_out, int out_size)
{
    const float* key_xyz      = (const float*)d_in[0];  // [4,16384,3]
    const float* key_features = (const float*)d_in[1];  // [4,64,16384]
    const float* query_box    = (const float*)d_in[2];  // [4,256,6]
    float* out = (float*)d_out;

    boxquery_group_kernel<<<B_ * NQ_, 256>>>(key_xyz, key_features, query_box, out);
}

// round 9
// speedup vs baseline: 1.5581x; 1.5581x over previous
#include <cuda_runtime.h>
#include <cstdint>

// Problem constants (fixed by reference setup_inputs)
#define B_   4
#define N_   16384
#define C_   64
#define NQ_  256
#define NS_  32

// Output layout (verified passing since R1):
//   grouped_xyz : [B, 3,   NQ, NS]
//   new_features: [B, 3+C, NQ, NS]
//   mask        : [B, NQ, NS]  (all False; index 0 can only land in slot 0,
//                               which the reference forces to False)

__global__ __launch_bounds__(256) void boxquery_group_kernel(
    const float* __restrict__ xyz,    // [B, N, 3]
    const float* __restrict__ feat,   // [B, C, N]
    const float* __restrict__ qbox,   // [B, NQ, 6]
    float* __restrict__ out)
{
    const int bq   = blockIdx.x;        // 0 .. B*NQ-1
    const int b    = bq >> 8;           // / NQ_
    const int q    = bq & (NQ_ - 1);
    const int tid  = threadIdx.x;
    const int lane = tid & 31;
    const int w    = tid >> 5;

    // Per-warp selected indices — each warp computes its own identical copy,
    // so the kernel needs NO block-level barrier at all.
    __shared__ int sidx_sh[8][NS_];

    const float*  xb  = xyz + (size_t)b * N_ * 3;
    const float2* xb2 = (const float2*)xb;       // batch base is 16B-aligned

    // ---- Front-batched independent loads: box (3x LDG.64) + first 64 pts ----
    const float2* box2 = (const float2*)(qbox + (size_t)(b * NQ_ + q) * 6);
    const float2 c01 = box2[0];   // cx, cy
    const float2 c23 = box2[1];   // cz, sx
    const float2 c45 = box2[2];   // sy, sz

    // lane ℓ holds points 2ℓ and 2ℓ+1 (floats 6ℓ..6ℓ+5)
    const float2 a0 = xb2[3 * lane + 0];   // x0, y0
    const float2 a1 = xb2[3 * lane + 1];   // z0, x1
    const float2 a2 = xb2[3 * lane + 2];   // y1, z1

    const float cx = c01.x, cy = c01.y, cz = c23.x;
    const float hx = 0.5f * c23.y, hy = 0.5f * c45.x, hz = 0.5f * c45.y;

    // predicate ("sort key == 0"): (n == 0) || !in_box(n)
    const bool inb0 = (fabsf(a0.x - cx) <= hx) & (fabsf(a0.y - cy) <= hy) &
                      (fabsf(a1.x - cz) <= hz);
    const bool inb1 = (fabsf(a1.y - cx) <= hx) & (fabsf(a2.x - cy) <= hy) &
                      (fabsf(a2.y - cz) <= hz);
    const bool acc0 = (lane == 0) || (!inb0);   // n = 2ℓ (n==0 only at lane 0)
    const bool acc1 = !inb1;                    // n = 2ℓ+1 ≥ 1 always

    // ---- Exact ranks via two ballots (no scan chain) ----
    const unsigned m0 = __ballot_sync(0xffffffffu, acc0);
    const unsigned m1 = __ballot_sync(0xffffffffu, acc1);
    const unsigned below = (1u << lane) - 1u;
    const int excl  = __popc(m0 & below) + __popc(m1 & below);
    const int total = __popc(m0) + __popc(m1);

    if (acc0 && excl < NS_)                    sidx_sh[w][excl]        = 2 * lane;
    if (acc1 && (excl + (int)acc0) < NS_)      sidx_sh[w][excl + acc0] = 2 * lane + 1;

    // ---- Fallback (statistically never taken): exact argsort order.
    // Continue zero-key scan over [64, N), then in-box (n>0) ascending. ----
    if (total < NS_) {
        int count = total, base = 64;
        while (count < NS_ && base < N_) {
            const int nn = base + lane;
            const bool inb = (fabsf(xb[nn*3+0] - cx) <= hx) &
                             (fabsf(xb[nn*3+1] - cy) <= hy) &
                             (fabsf(xb[nn*3+2] - cz) <= hz);
            const bool acc = !inb;   // nn > 0 guaranteed
            const unsigned m   = __ballot_sync(0xffffffffu, acc);
            const int      pre = __popc(m & below);
            if (acc && (count + pre) < NS_) sidx_sh[w][count + pre] = nn;
            count += __popc(m);
            base  += 32;
        }
        base = 0;
        while (count < NS_ && base < N_) {
            const int nn = base + lane;
            const bool inb = (fabsf(xb[nn*3+0] - cx) <= hx) &
                             (fabsf(xb[nn*3+1] - cy) <= hy) &
                             (fabsf(xb[nn*3+2] - cz) <= hz);
            const bool acc = (nn != 0) && inb;
            const unsigned m   = __ballot_sync(0xffffffffu, acc);
            const int      pre = __popc(m & below);
            if (acc && (count + pre) < NS_) sidx_sh[w][count + pre] = nn;
            count += __popc(m);
            base  += 32;
        }
    }
    __syncwarp();
    const int n = sidx_sh[w][lane];      // index for slot k = lane (ascending)

    // ---- Output pointers ----
    float* out_gx = out;                                        // [B,3,NQ,NS]
    float* out_nf = out + (size_t)B_ * 3 * NQ_ * NS_;           // [B,3+C,NQ,NS]
    float* out_mk = out_nf + (size_t)B_ * (3 + C_) * NQ_ * NS_; // [B,NQ,NS]

    // ---- Warp 0: grouped_xyz rows (both tensors) + mask, straight stores ----
    if (w == 0) {
        // gather xyz[n] — n spans ~2 cache lines, L1-resident
        const float gx = xb[n * 3 + 0] - cx;
        const float gy = xb[n * 3 + 1] - cy;
        const float gz = xb[n * 3 + 2] - cz;
        const size_t gx_row = ((size_t)(b * 3 + 0) * NQ_ + q) * NS_ + lane;
        const size_t nf_row = ((size_t)(b * (3 + C_) + 0) * NQ_ + q) * NS_ + lane;
        const size_t row_pitch = (size_t)NQ_ * NS_;
        out_gx[gx_row + 0 * row_pitch] = gx;
        out_gx[gx_row + 1 * row_pitch] = gy;
        out_gx[gx_row + 2 * row_pitch] = gz;
        out_nf[nf_row + 0 * row_pitch] = gx;
        out_nf[nf_row + 1 * row_pitch] = gy;
        out_nf[nf_row + 2 * row_pitch] = gz;
        out_mk[(size_t)(b * NQ_ + q) * NS_ + lane] = 0.0f;
    }

    // ---- Features: warp w -> channels 8w..8w+7; lane = slot.
    // Each LDG.32 stays within ONE channel row => ~2 L1 wavefronts/instr. ----
    const float* fb  = feat + (size_t)b * C_ * N_ + (size_t)(8 * w) * N_;
    float* nf_ch = out_nf + ((size_t)(b * (3 + C_) + 3 + 8 * w) * NQ_ + q) * NS_ + lane;

    float vals[8];
    #pragma unroll
    for (int j = 0; j < 8; ++j)
        vals[j] = fb[(size_t)j * N_ + n];            // 8 independent gathers (MLP)
    #pragma unroll
    for (int j = 0; j < 8; ++j)
        nf_ch[(size_t)j * NQ_ * NS_] = vals[j];      // warp-coalesced STG.32
}

extern "C" void kernel_launch(void* const* d_in, const int* in_sizes, int n_in,
                              void* d_out, int out_size)
{
    const float* key_xyz      = (const float*)d_in[0];  // [4,16384,3]
    const float* key_features = (const float*)d_in[1];  // [4,64,16384]
    const float* query_box    = (const float*)d_in[2];  // [4,256,6]
    float* out = (float*)d_out;

    boxquery_group_kernel<<<B_ * NQ_, 256>>>(key_xyz, key_features, query_box, out);
}

// round 10
// speedup vs baseline: 1.6184x; 1.0386x over previous
#include <cuda_runtime.h>
#include <cstdint>

// Problem constants (fixed by reference setup_inputs)
#define B_   4
#define N_   16384
#define C_   64
#define NQ_  256
#define NS_  32

// Output layout (verified passing since R1):
//   grouped_xyz : [B, 3,   NQ, NS]
//   new_features: [B, 3+C, NQ, NS]
//   mask        : [B, NQ, NS]  (all False; index 0 can only land in slot 0,
//                               which the reference forces to False)
//
// Structure: 512 CTAs, each handles TWO queries of the same batch.
// The first-64-point xyz prefix is shared by both queries (loaded once per
// warp); the two queries' selection + gather chains are interleaved for MLP.

__global__ __launch_bounds__(256) void boxquery_group_kernel(
    const float* __restrict__ xyz,    // [B, N, 3]
    const float* __restrict__ feat,   // [B, C, N]
    const float* __restrict__ qbox,   // [B, NQ, 6]
    float* __restrict__ out)
{
    const int cta  = blockIdx.x;        // 0 .. 511
    const int b    = cta >> 7;          // 128 CTAs per batch
    const int q0   = (cta & 127) << 1;  // queries q0, q0+1
    const int tid  = threadIdx.x;
    const int lane = tid & 31;
    const int w    = tid >> 5;

    // Per-warp selected indices for the two queries (warp-autonomous; the
    // kernel has NO block-level barrier).
    __shared__ int sidx_sh[8][2][NS_];

    const float*  xb  = xyz + (size_t)b * N_ * 3;
    const float2* xb2 = (const float2*)xb;       // batch base is 16B-aligned

    // ---- Front-batched independent loads: 2 boxes + first 64 points ----
    const float2* boxA = (const float2*)(qbox + (size_t)(b * NQ_ + q0) * 6);
    const float2 A01 = boxA[0], A23 = boxA[1], A45 = boxA[2];
    const float2 B01 = boxA[3], B23 = boxA[4], B45 = boxA[5];  // q0+1 follows

    // lane ℓ holds points 2ℓ and 2ℓ+1 (floats 6ℓ..6ℓ+5)
    const float2 a0 = xb2[3 * lane + 0];   // x0, y0
    const float2 a1 = xb2[3 * lane + 1];   // z0, x1
    const float2 a2 = xb2[3 * lane + 2];   // y1, z1

    const float cxA = A01.x, cyA = A01.y, czA = A23.x;
    const float hxA = 0.5f * A23.y, hyA = 0.5f * A45.x, hzA = 0.5f * A45.y;
    const float cxB = B01.x, cyB = B01.y, czB = B23.x;
    const float hxB = 0.5f * B23.y, hyB = 0.5f * B45.x, hzB = 0.5f * B45.y;

    const unsigned below = (1u << lane) - 1u;

    // ---- Selection for both queries (predicate: (n==0) || !in_box(n)) ----
    int totals[2];
    {
        // query A
        const bool inb0A = (fabsf(a0.x - cxA) <= hxA) & (fabsf(a0.y - cyA) <= hyA) &
                           (fabsf(a1.x - czA) <= hzA);
        const bool inb1A = (fabsf(a1.y - cxA) <= hxA) & (fabsf(a2.x - cyA) <= hyA) &
                           (fabsf(a2.y - czA) <= hzA);
        const bool acc0 = (lane == 0) || (!inb0A);
        const bool acc1 = !inb1A;
        const unsigned m0 = __ballot_sync(0xffffffffu, acc0);
        const unsigned m1 = __ballot_sync(0xffffffffu, acc1);
        const int excl = __popc(m0 & below) + __popc(m1 & below);
        totals[0] = __popc(m0) + __popc(m1);
        if (acc0 && excl < NS_)               sidx_sh[w][0][excl]        = 2 * lane;
        if (acc1 && (excl + (int)acc0) < NS_) sidx_sh[w][0][excl + acc0] = 2 * lane + 1;
    }
    {
        // query B
        const bool inb0B = (fabsf(a0.x - cxB) <= hxB) & (fabsf(a0.y - cyB) <= hyB) &
                           (fabsf(a1.x - czB) <= hzB);
        const bool inb1B = (fabsf(a1.y - cxB) <= hxB) & (fabsf(a2.x - cyB) <= hyB) &
                           (fabsf(a2.y - czB) <= hzB);
        const bool acc0 = (lane == 0) || (!inb0B);
        const bool acc1 = !inb1B;
        const unsigned m0 = __ballot_sync(0xffffffffu, acc0);
        const unsigned m1 = __ballot_sync(0xffffffffu, acc1);
        const int excl = __popc(m0 & below) + __popc(m1 & below);
        totals[1] = __popc(m0) + __popc(m1);
        if (acc0 && excl < NS_)               sidx_sh[w][1][excl]        = 2 * lane;
        if (acc1 && (excl + (int)acc0) < NS_) sidx_sh[w][1][excl + acc0] = 2 * lane + 1;
    }

    // ---- Fallback (statistically never taken): exact argsort order.
    // Continue zero-key scan over [64, N), then in-box (n>0) ascending. ----
    #pragma unroll
    for (int j = 0; j < 2; ++j) {
        if (totals[j] < NS_) {
            const float cx = j ? cxB : cxA, cy = j ? cyB : cyA, cz = j ? czB : czA;
            const float hx = j ? hxB : hxA, hy = j ? hyB : hyA, hz = j ? hzB : hzA;
            int count = totals[j], base = 64;
            while (count < NS_ && base < N_) {
                const int nn = base + lane;
                const bool inb = (fabsf(xb[nn*3+0] - cx) <= hx) &
                                 (fabsf(xb[nn*3+1] - cy) <= hy) &
                                 (fabsf(xb[nn*3+2] - cz) <= hz);
                const bool acc = !inb;   // nn > 0 guaranteed
                const unsigned m   = __ballot_sync(0xffffffffu, acc);
                const int      pre = __popc(m & below);
                if (acc && (count + pre) < NS_) sidx_sh[w][j][count + pre] = nn;
                count += __popc(m);
                base  += 32;
            }
            base = 0;
            while (count < NS_ && base < N_) {
                const int nn = base + lane;
                const bool inb = (fabsf(xb[nn*3+0] - cx) <= hx) &
                                 (fabsf(xb[nn*3+1] - cy) <= hy) &
                                 (fabsf(xb[nn*3+2] - cz) <= hz);
                const bool acc = (nn != 0) && inb;
                const unsigned m   = __ballot_sync(0xffffffffu, acc);
                const int      pre = __popc(m & below);
                if (acc && (count + pre) < NS_) sidx_sh[w][j][count + pre] = nn;
                count += __popc(m);
                base  += 32;
            }
        }
    }
    __syncwarp();
    const int n0 = sidx_sh[w][0][lane];   // slot k = lane, query q0
    const int n1 = sidx_sh[w][1][lane];   // slot k = lane, query q0+1

    // ---- Output pointers ----
    float* out_gx = out;                                        // [B,3,NQ,NS]
    float* out_nf = out + (size_t)B_ * 3 * NQ_ * NS_;           // [B,3+C,NQ,NS]
    float* out_mk = out_nf + (size_t)B_ * (3 + C_) * NQ_ * NS_; // [B,NQ,NS]
    const size_t row_pitch = (size_t)NQ_ * NS_;

    // ---- Warps 0 and 1: grouped_xyz rows (both tensors) + mask ----
    if (w < 2) {
        const int q = q0 + w;
        const int n = w ? n1 : n0;
        const float cx = w ? cxB : cxA, cy = w ? cyB : cyA, cz = w ? czB : czA;
        const float gx = xb[n * 3 + 0] - cx;   // ~2 cache lines, L1-resident
        const float gy = xb[n * 3 + 1] - cy;
        const float gz = xb[n * 3 + 2] - cz;
        const size_t gx_row = ((size_t)(b * 3 + 0) * NQ_ + q) * NS_ + lane;
        const size_t nf_row = ((size_t)(b * (3 + C_) + 0) * NQ_ + q) * NS_ + lane;
        out_gx[gx_row + 0 * row_pitch] = gx;
        out_gx[gx_row + 1 * row_pitch] = gy;
        out_gx[gx_row + 2 * row_pitch] = gz;
        out_nf[nf_row + 0 * row_pitch] = gx;
        out_nf[nf_row + 1 * row_pitch] = gy;
        out_nf[nf_row + 2 * row_pitch] = gz;
        out_mk[(size_t)(b * NQ_ + q) * NS_ + lane] = 0.0f;
    }

    // ---- Features: warp w -> channels 8w..8w+7, both queries interleaved.
    // Each LDG.32 stays within ONE channel row (~2 L1 wavefronts/instr);
    // 16 independent gathers in flight per warp (MLP). ----
    const float* fb = feat + (size_t)b * C_ * N_ + (size_t)(8 * w) * N_;
    float* nfA = out_nf + ((size_t)(b * (3 + C_) + 3 + 8 * w) * NQ_ + q0)     * NS_ + lane;
    float* nfB = out_nf + ((size_t)(b * (3 + C_) + 3 + 8 * w) * NQ_ + q0 + 1) * NS_ + lane;

    float v0[8], v1[8];
    #pragma unroll
    for (int j = 0; j < 8; ++j) {
        v0[j] = fb[(size_t)j * N_ + n0];
        v1[j] = fb[(size_t)j * N_ + n1];
    }
    #pragma unroll
    for (int j = 0; j < 8; ++j) {
        nfA[(size_t)j * row_pitch] = v0[j];     // warp-coalesced STG.32
        nfB[(size_t)j * row_pitch] = v1[j];
    }
}

extern "C" void kernel_launch(void* const* d_in, const int* in_sizes, int n_in,
                              void* d_out, int out_size)
{
    const float* key_xyz      = (const float*)d_in[0];  // [4,16384,3]
    const float* key_features = (const float*)d_in[1];  // [4,64,16384]
    const float* query_box    = (const float*)d_in[2];  // [4,256,6]
    float* out = (float*)d_out;

    boxquery_group_kernel<<<(B_ * NQ_) / 2, 256>>>(key_xyz, key_features, query_box, out);
}